// round 1
// baseline (speedup 1.0000x reference)
#include <cuda_runtime.h>
#include <cuda_bf16.h>

// Problem constants
#define BB 2
#define TT 2048
#define DM 1024
#define HH 16
#define HD 64
#define MROWS (BB*TT)          // 4096
#define QKV_N (3*DM)           // 3072

// Scratch (device globals: no allocation allowed in kernel_launch)
__device__ float g_qkv[(size_t)MROWS * QKV_N];   // [4096, 3072] : Q|K|V per token row
__device__ float g_ao [(size_t)MROWS * DM];      // [4096, 1024] : attention out, [b,t,h,d]

// ---------------------------------------------------------------------------
// Generic fp32 SGEMM: C[M,N] = A[M,K] @ B[K,N], row-major.
// 128x128 block tile, BK=16, 256 threads, 8x8 per-thread microtile.
// Requires M%128==0, N%128==0, K%16==0 (true for all three GEMMs here).
// ---------------------------------------------------------------------------
__global__ __launch_bounds__(256) void sgemm_kernel(
    const float* __restrict__ A, const float* __restrict__ B,
    float* __restrict__ C, int M, int N, int K)
{
    __shared__ float As[16][128 + 4];   // stored transposed: As[k][m]
    __shared__ float Bs[16][128 + 4];

    const int tid = threadIdx.x;
    const int bx = blockIdx.x;          // N tile
    const int by = blockIdx.y;          // M tile
    const int tx = tid & 15;            // 16 col-groups
    const int ty = tid >> 4;            // 16 row-groups

    const float* Ab = A + (size_t)by * 128 * K;
    const float* Bb = B + (size_t)bx * 128;

    float acc[8][8];
#pragma unroll
    for (int i = 0; i < 8; i++)
#pragma unroll
        for (int j = 0; j < 8; j++) acc[i][j] = 0.f;

    for (int k0 = 0; k0 < K; k0 += 16) {
        // Load A tile 128x16 (512 float4, 2 per thread), store transposed
#pragma unroll
        for (int t = 0; t < 2; t++) {
            int f = tid + t * 256;          // 0..511
            int r = f >> 2;                 // row 0..127
            int c = (f & 3) * 4;            // col 0,4,8,12
            float4 v = *reinterpret_cast<const float4*>(Ab + (size_t)r * K + k0 + c);
            As[c + 0][r] = v.x; As[c + 1][r] = v.y;
            As[c + 2][r] = v.z; As[c + 3][r] = v.w;
        }
        // Load B tile 16x128 (512 float4, 2 per thread)
#pragma unroll
        for (int t = 0; t < 2; t++) {
            int f = tid + t * 256;
            int r = f >> 5;                 // row 0..15
            int c = (f & 31) * 4;           // col 0..124
            *reinterpret_cast<float4*>(&Bs[r][c]) =
                *reinterpret_cast<const float4*>(Bb + (size_t)(k0 + r) * N + c);
        }
        __syncthreads();

#pragma unroll
        for (int k = 0; k < 16; k++) {
            float a[8], b[8];
            *reinterpret_cast<float4*>(a)     = *reinterpret_cast<const float4*>(&As[k][ty * 8]);
            *reinterpret_cast<float4*>(a + 4) = *reinterpret_cast<const float4*>(&As[k][ty * 8 + 4]);
            *reinterpret_cast<float4*>(b)     = *reinterpret_cast<const float4*>(&Bs[k][tx * 8]);
            *reinterpret_cast<float4*>(b + 4) = *reinterpret_cast<const float4*>(&Bs[k][tx * 8 + 4]);
#pragma unroll
            for (int i = 0; i < 8; i++)
#pragma unroll
                for (int j = 0; j < 8; j++)
                    acc[i][j] = fmaf(a[i], b[j], acc[i][j]);
        }
        __syncthreads();
    }

#pragma unroll
    for (int i = 0; i < 8; i++) {
        int r = by * 128 + ty * 8 + i;
        float* Cp = C + (size_t)r * N + bx * 128 + tx * 8;
        float4 v0 = {acc[i][0], acc[i][1], acc[i][2], acc[i][3]};
        float4 v1 = {acc[i][4], acc[i][5], acc[i][6], acc[i][7]};
        *reinterpret_cast<float4*>(Cp)     = v0;
        *reinterpret_cast<float4*>(Cp + 4) = v1;
    }
}

// ---------------------------------------------------------------------------
// Flash attention: one CTA per (b, h, 64-row q tile). 128 threads.
// Thread grid 16 (row groups of 4) x 8 (col groups of 8).
// Reads q/k/v directly out of g_qkv (col offsets 0 / 1024 / 2048).
// Writes g_ao in [b, t, h, d] layout (i.e. already transposed for the proj).
// ---------------------------------------------------------------------------
#define SMP (HD + 4)   // padded row stride: 68 floats

__global__ __launch_bounds__(128) void attn_kernel(
    const float* __restrict__ qkv, float* __restrict__ ao)
{
    extern __shared__ float sm[];
    float* qs = sm;                 // [64][SMP]
    float* ks = qs + 64 * SMP;
    float* vs = ks + 64 * SMP;
    float* ps = vs + 64 * SMP;

    const int qt = blockIdx.x;
    const int h  = blockIdx.y;
    const int b  = blockIdx.z;
    const int tid = threadIdx.x;
    const int tx = tid & 7;         // 0..7 (8 col groups)
    const int ty = tid >> 3;        // 0..15 (16 row groups)

    const float* qb = qkv + ((size_t)(b * TT + qt * 64)) * QKV_N + h * HD;
    const float* kb = qkv + ((size_t)(b * TT)) * QKV_N + DM     + h * HD;
    const float* vb = kb + DM;

    // Load q tile, folding in the muP 1/head_dim scale
    const float qscale = 1.0f / (float)HD;
    for (int f = tid; f < 64 * 16; f += 128) {   // 64 rows x 16 float4
        int r = f >> 4;
        int c = (f & 15) * 4;
        float4 v = *reinterpret_cast<const float4*>(qb + (size_t)r * QKV_N + c);
        qs[r * SMP + c + 0] = v.x * qscale;
        qs[r * SMP + c + 1] = v.y * qscale;
        qs[r * SMP + c + 2] = v.z * qscale;
        qs[r * SMP + c + 3] = v.w * qscale;
    }

    float m[4], l[4], o[4][8];
#pragma unroll
    for (int i = 0; i < 4; i++) {
        m[i] = -1e30f; l[i] = 0.f;
#pragma unroll
        for (int j = 0; j < 8; j++) o[i][j] = 0.f;
    }

    for (int kt = 0; kt < TT / 64; kt++) {
        // Load k and v tiles
        for (int f = tid; f < 64 * 16; f += 128) {
            int r = f >> 4;
            int c = (f & 15) * 4;
            size_t off = (size_t)(kt * 64 + r) * QKV_N + c;
            *reinterpret_cast<float4*>(&ks[r * SMP + c]) =
                *reinterpret_cast<const float4*>(kb + off);
            *reinterpret_cast<float4*>(&vs[r * SMP + c]) =
                *reinterpret_cast<const float4*>(vb + off);
        }
        __syncthreads();

        // S = (q * 1/64) @ k^T   -> s[4][8]
        float s[4][8];
#pragma unroll
        for (int i = 0; i < 4; i++)
#pragma unroll
            for (int j = 0; j < 8; j++) s[i][j] = 0.f;

#pragma unroll 8
        for (int d = 0; d < 64; d++) {
            float a[4], bv[8];
#pragma unroll
            for (int i = 0; i < 4; i++) a[i] = qs[(ty * 4 + i) * SMP + d];
#pragma unroll
            for (int j = 0; j < 8; j++) bv[j] = ks[(tx * 8 + j) * SMP + d];
#pragma unroll
            for (int i = 0; i < 4; i++)
#pragma unroll
                for (int j = 0; j < 8; j++)
                    s[i][j] = fmaf(a[i], bv[j], s[i][j]);
        }

        // Online softmax (row stats shared across the 8 tx lanes via shuffles;
        // lanes with equal ty are 8 consecutive lanes in a warp)
#pragma unroll
        for (int i = 0; i < 4; i++) {
            float rm = s[i][0];
#pragma unroll
            for (int j = 1; j < 8; j++) rm = fmaxf(rm, s[i][j]);
            rm = fmaxf(rm, __shfl_xor_sync(0xffffffffu, rm, 1));
            rm = fmaxf(rm, __shfl_xor_sync(0xffffffffu, rm, 2));
            rm = fmaxf(rm, __shfl_xor_sync(0xffffffffu, rm, 4));
            float mn = fmaxf(m[i], rm);
            float corr = __expf(m[i] - mn);
            float rs = 0.f;
#pragma unroll
            for (int j = 0; j < 8; j++) {
                float p = __expf(s[i][j] - mn);
                s[i][j] = p;
                rs += p;
            }
            rs += __shfl_xor_sync(0xffffffffu, rs, 1);
            rs += __shfl_xor_sync(0xffffffffu, rs, 2);
            rs += __shfl_xor_sync(0xffffffffu, rs, 4);
            l[i] = l[i] * corr + rs;
            m[i] = mn;
#pragma unroll
            for (int j = 0; j < 8; j++) o[i][j] *= corr;
        }

        // Stage P for the second GEMM
#pragma unroll
        for (int i = 0; i < 4; i++)
#pragma unroll
            for (int j = 0; j < 8; j++)
                ps[(ty * 4 + i) * SMP + tx * 8 + j] = s[i][j];
        __syncthreads();

        // O += P @ V
#pragma unroll 8
        for (int kp = 0; kp < 64; kp++) {
            float a[4], bv[8];
#pragma unroll
            for (int i = 0; i < 4; i++) a[i] = ps[(ty * 4 + i) * SMP + kp];
#pragma unroll
            for (int j = 0; j < 8; j++) bv[j] = vs[kp * SMP + tx * 8 + j];
#pragma unroll
            for (int i = 0; i < 4; i++)
#pragma unroll
                for (int j = 0; j < 8; j++)
                    o[i][j] = fmaf(a[i], bv[j], o[i][j]);
        }
        __syncthreads();   // protects ks/vs/ps for next iteration
    }

    // Normalize and write out in [b, t, h, d] layout
#pragma unroll
    for (int i = 0; i < 4; i++) {
        float inv = 1.0f / l[i];
        int t = qt * 64 + ty * 4 + i;
        float* op = ao + ((size_t)(b * TT + t)) * DM + h * HD + tx * 8;
        float4 v0 = {o[i][0] * inv, o[i][1] * inv, o[i][2] * inv, o[i][3] * inv};
        float4 v1 = {o[i][4] * inv, o[i][5] * inv, o[i][6] * inv, o[i][7] * inv};
        *reinterpret_cast<float4*>(op)     = v0;
        *reinterpret_cast<float4*>(op + 4) = v1;
    }
}

// ---------------------------------------------------------------------------
// Launch
// ---------------------------------------------------------------------------
extern "C" void kernel_launch(void* const* d_in, const int* in_sizes, int n_in,
                              void* d_out, int out_size)
{
    const float* x     = (const float*)d_in[0];   // [2, 2048, 1024]
    const float* wqkv  = (const float*)d_in[1];   // [1024, 3072]
    const float* wproj = (const float*)d_in[2];   // [1024, 1024]
    float* out = (float*)d_out;                   // [2, 2048, 1024]

    float* qkv; cudaGetSymbolAddress((void**)&qkv, g_qkv);
    float* ao;  cudaGetSymbolAddress((void**)&ao,  g_ao);

    // 1) QKV GEMM: [4096,1024] @ [1024,3072]
    {
        dim3 grid(QKV_N / 128, MROWS / 128);
        sgemm_kernel<<<grid, 256>>>(x, wqkv, qkv, MROWS, QKV_N, DM);
    }

    // 2) Flash attention
    {
        int smem = 4 * 64 * SMP * (int)sizeof(float);   // ~69.6 KB
        cudaFuncSetAttribute(attn_kernel,
                             cudaFuncAttributeMaxDynamicSharedMemorySize, smem);
        dim3 grid(TT / 64, HH, BB);
        attn_kernel<<<grid, 128, smem>>>(qkv, ao);
    }

    // 3) Output projection: [4096,1024] @ [1024,1024]
    {
        dim3 grid(DM / 128, MROWS / 128);
        sgemm_kernel<<<grid, 256>>>(ao, wproj, out, MROWS, DM, DM);
    }
}

// round 2
// speedup vs baseline: 5.3158x; 5.3158x over previous
#include <cuda_runtime.h>
#include <cuda_bf16.h>
#include <cstdint>

// Problem constants
#define BB 2
#define TT 2048
#define DM 1024
#define HH 16
#define HD 64
#define MROWS (BB*TT)          // 4096
#define QKV_N (3*DM)           // 3072

// ---------------------------------------------------------------------------
// Device scratch (static; no runtime allocation allowed)
// ---------------------------------------------------------------------------
__device__ float g_qkv[(size_t)MROWS * QKV_N];            // fp32 QKV
__device__ float g_ao [(size_t)MROWS * DM];               // fp32 attention out [b,t,h,d]

__device__ __nv_bfloat16 g_xh[(size_t)MROWS * DM],  g_xl[(size_t)MROWS * DM];
__device__ __nv_bfloat16 g_wqkvh[(size_t)QKV_N * DM], g_wqkvl[(size_t)QKV_N * DM];   // [N][K]
__device__ __nv_bfloat16 g_wprojh[(size_t)DM * DM],  g_wprojl[(size_t)DM * DM];      // [N][K]
__device__ __nv_bfloat16 g_qkvh[(size_t)MROWS * QKV_N], g_qkvl[(size_t)MROWS * QKV_N];
__device__ __nv_bfloat16 g_vth[(size_t)BB*HH*HD*TT], g_vtl[(size_t)BB*HH*HD*TT];     // [b,h,d,t]
__device__ __nv_bfloat16 g_aoh[(size_t)MROWS * DM], g_aol[(size_t)MROWS * DM];

// ---------------------------------------------------------------------------
// Helpers
// ---------------------------------------------------------------------------
__device__ __forceinline__ uint32_t lds32(const __nv_bfloat16* p) {
    return *reinterpret_cast<const uint32_t*>(p);
}

__device__ __forceinline__ void cpasync16(void* smem_ptr, const void* gptr) {
    uint32_t s = (uint32_t)__cvta_generic_to_shared(smem_ptr);
    asm volatile("cp.async.cg.shared.global [%0], [%1], 16;\n" :: "r"(s), "l"(gptr));
}
#define CP_COMMIT asm volatile("cp.async.commit_group;\n")
#define CP_WAIT1  asm volatile("cp.async.wait_group 1;\n")
#define CP_WAIT0  asm volatile("cp.async.wait_group 0;\n")

__device__ __forceinline__ void mma16816(float* d, const uint32_t* a, const uint32_t* b) {
    asm volatile(
        "mma.sync.aligned.m16n8k16.row.col.f32.bf16.bf16.f32 "
        "{%0,%1,%2,%3}, {%4,%5,%6,%7}, {%8,%9}, {%0,%1,%2,%3};\n"
        : "+f"(d[0]), "+f"(d[1]), "+f"(d[2]), "+f"(d[3])
        : "r"(a[0]), "r"(a[1]), "r"(a[2]), "r"(a[3]), "r"(b[0]), "r"(b[1]));
}

__device__ __forceinline__ void split2(float x, float y, uint32_t& h, uint32_t& l) {
    __nv_bfloat162 hv, lv;
    hv.x = __float2bfloat16_rn(x);
    hv.y = __float2bfloat16_rn(y);
    lv.x = __float2bfloat16_rn(x - __bfloat162float(hv.x));
    lv.y = __float2bfloat16_rn(y - __bfloat162float(hv.y));
    h = reinterpret_cast<uint32_t&>(hv);
    l = reinterpret_cast<uint32_t&>(lv);
}

// ---------------------------------------------------------------------------
// Conversions
// ---------------------------------------------------------------------------
__global__ void cvt_split(const float4* __restrict__ in,
                          __nv_bfloat162* __restrict__ hi,
                          __nv_bfloat162* __restrict__ lo, int n4)
{
    int i = blockIdx.x * blockDim.x + threadIdx.x;
    if (i >= n4) return;
    float4 v = in[i];
    __nv_bfloat162 h0, h1, l0, l1;
    h0.x = __float2bfloat16_rn(v.x); h0.y = __float2bfloat16_rn(v.y);
    h1.x = __float2bfloat16_rn(v.z); h1.y = __float2bfloat16_rn(v.w);
    l0.x = __float2bfloat16_rn(v.x - __bfloat162float(h0.x));
    l0.y = __float2bfloat16_rn(v.y - __bfloat162float(h0.y));
    l1.x = __float2bfloat16_rn(v.z - __bfloat162float(h1.x));
    l1.y = __float2bfloat16_rn(v.w - __bfloat162float(h1.y));
    hi[2*i] = h0; hi[2*i+1] = h1;
    lo[2*i] = l0; lo[2*i+1] = l1;
}

// W [K,N] fp32  ->  Wt hi/lo [N,K] bf16
__global__ void cvt_wT(const float* __restrict__ w,
                       __nv_bfloat16* __restrict__ th,
                       __nv_bfloat16* __restrict__ tl, int K, int N)
{
    __shared__ float t[32][33];
    int bx = blockIdx.x, by = blockIdx.y;
    int tx = threadIdx.x, ty = threadIdx.y;
#pragma unroll
    for (int j = 0; j < 32; j += 8)
        t[ty + j][tx] = w[(size_t)(by*32 + ty + j) * N + bx*32 + tx];
    __syncthreads();
#pragma unroll
    for (int j = 0; j < 32; j += 8) {
        float v = t[tx][ty + j];
        size_t o = (size_t)(bx*32 + ty + j) * K + by*32 + tx;
        __nv_bfloat16 h = __float2bfloat16_rn(v);
        th[o] = h;
        tl[o] = __float2bfloat16_rn(v - __bfloat162float(h));
    }
}

// g_qkv fp32 -> vT hi/lo [b,h,d,t]
__global__ void cvt_vT(const float* __restrict__ qkv,
                       __nv_bfloat16* __restrict__ th,
                       __nv_bfloat16* __restrict__ tl)
{
    __shared__ float t[32][33];
    int bh = blockIdx.z;                 // b*16 + h
    int b = bh >> 4, h = bh & 15;
    int t0 = blockIdx.x * 32, d0 = blockIdx.y * 32;
    int tx = threadIdx.x, ty = threadIdx.y;
#pragma unroll
    for (int j = 0; j < 32; j += 8)
        t[ty + j][tx] = qkv[(size_t)(b*TT + t0 + ty + j) * QKV_N + 2*DM + h*HD + d0 + tx];
    __syncthreads();
#pragma unroll
    for (int j = 0; j < 32; j += 8) {
        float v = t[tx][ty + j];
        size_t o = (size_t)(bh*HD + d0 + ty + j) * TT + t0 + tx;
        __nv_bfloat16 hh = __float2bfloat16_rn(v);
        th[o] = hh;
        tl[o] = __float2bfloat16_rn(v - __bfloat162float(hh));
    }
}

// ---------------------------------------------------------------------------
// Split-bf16 GEMM: C[M,N] fp32 = A@B using Ah,Al [M,K]; Bh,Bl [N,K] (k-major)
// 128x128 CTA tile, 256 threads (8 warps, 4x2), k-step 32, cp.async dbuf.
// ---------------------------------------------------------------------------
#define GPAD 40
#define GBUF (4*128*GPAD)   // elems per buffer (Ah|Al|Bh|Bl)

__global__ __launch_bounds__(256) void gemm_bf16s(
    const __nv_bfloat16* __restrict__ Ah, const __nv_bfloat16* __restrict__ Al,
    const __nv_bfloat16* __restrict__ Bh, const __nv_bfloat16* __restrict__ Bl,
    float* __restrict__ C, int M, int N, int K)
{
    extern __shared__ __nv_bfloat16 sm[];
    const int tid  = threadIdx.x;
    const int wid  = tid >> 5, lane = tid & 31;
    const int gid  = lane >> 2, tg = lane & 3;
    const int wm   = wid & 3,  wn  = wid >> 2;
    const int m0   = blockIdx.y * 128, n0 = blockIdx.x * 128;
    const int NS   = K >> 5;

    float acc[2][8][4];
#pragma unroll
    for (int mt = 0; mt < 2; mt++)
#pragma unroll
        for (int nt = 0; nt < 8; nt++)
#pragma unroll
            for (int i = 0; i < 4; i++) acc[mt][nt][i] = 0.f;

    // loader: 512 uint4 per half-matrix, 2 per thread
    auto issue = [&](int ks, int buf) {
        __nv_bfloat16* s = sm + buf * GBUF;
        int k0 = ks * 32;
#pragma unroll
        for (int t = 0; t < 2; t++) {
            int e = tid + t * 256;
            int r = e >> 2, c = (e & 3) * 8;
            cpasync16(s +                 r*GPAD + c, Ah + (size_t)(m0 + r)*K + k0 + c);
            cpasync16(s + 128*GPAD     +  r*GPAD + c, Al + (size_t)(m0 + r)*K + k0 + c);
            cpasync16(s + 2*128*GPAD   +  r*GPAD + c, Bh + (size_t)(n0 + r)*K + k0 + c);
            cpasync16(s + 3*128*GPAD   +  r*GPAD + c, Bl + (size_t)(n0 + r)*K + k0 + c);
        }
    };

    issue(0, 0); CP_COMMIT;

    for (int ks = 0; ks < NS; ks++) {
        int buf = ks & 1;
        if (ks + 1 < NS) { issue(ks + 1, buf ^ 1); CP_COMMIT; CP_WAIT1; }
        else             { CP_WAIT0; }
        __syncthreads();

        const __nv_bfloat16* sAh = sm + buf * GBUF;
        const __nv_bfloat16* sAl = sAh + 128*GPAD;
        const __nv_bfloat16* sBh = sAh + 2*128*GPAD;
        const __nv_bfloat16* sBl = sAh + 3*128*GPAD;

#pragma unroll
        for (int kt = 0; kt < 2; kt++) {
            int kb = kt * 16 + 2 * tg;
            uint32_t ah[2][4], al[2][4];
#pragma unroll
            for (int mt = 0; mt < 2; mt++) {
                int r = wm*32 + mt*16 + gid;
                ah[mt][0] = lds32(sAh + r*GPAD + kb);
                ah[mt][1] = lds32(sAh + (r+8)*GPAD + kb);
                ah[mt][2] = lds32(sAh + r*GPAD + kb + 8);
                ah[mt][3] = lds32(sAh + (r+8)*GPAD + kb + 8);
                al[mt][0] = lds32(sAl + r*GPAD + kb);
                al[mt][1] = lds32(sAl + (r+8)*GPAD + kb);
                al[mt][2] = lds32(sAl + r*GPAD + kb + 8);
                al[mt][3] = lds32(sAl + (r+8)*GPAD + kb + 8);
            }
            uint32_t bh[8][2], bl[8][2];
#pragma unroll
            for (int nt = 0; nt < 8; nt++) {
                int rn = wn*64 + nt*8 + gid;
                bh[nt][0] = lds32(sBh + rn*GPAD + kb);
                bh[nt][1] = lds32(sBh + rn*GPAD + kb + 8);
                bl[nt][0] = lds32(sBl + rn*GPAD + kb);
                bl[nt][1] = lds32(sBl + rn*GPAD + kb + 8);
            }
#pragma unroll
            for (int mt = 0; mt < 2; mt++)
#pragma unroll
                for (int nt = 0; nt < 8; nt++) {
                    mma16816(acc[mt][nt], ah[mt], bh[nt]);
                    mma16816(acc[mt][nt], ah[mt], bl[nt]);
                    mma16816(acc[mt][nt], al[mt], bh[nt]);
                }
        }
        __syncthreads();
    }

#pragma unroll
    for (int mt = 0; mt < 2; mt++)
#pragma unroll
        for (int nt = 0; nt < 8; nt++) {
            int r = m0 + wm*32 + mt*16 + gid;
            int c = n0 + wn*64 + nt*8 + 2*tg;
            float2 v0 = make_float2(acc[mt][nt][0], acc[mt][nt][1]);
            float2 v1 = make_float2(acc[mt][nt][2], acc[mt][nt][3]);
            *reinterpret_cast<float2*>(C + (size_t)r*N + c)     = v0;
            *reinterpret_cast<float2*>(C + (size_t)(r+8)*N + c) = v1;
        }
}

// ---------------------------------------------------------------------------
// Flash attention, split-bf16 tensor cores.
// CTA: 128 q rows of one (b,h); 8 warps, each owns 16 q rows (independent
// softmax). Key loop: 64 keys/step, cp.async double-buffered K and V^T tiles.
// ---------------------------------------------------------------------------
#define APAD 72
#define ABUF (4*64*APAD)    // Kh|Kl|Vh|Vl per buffer

__global__ __launch_bounds__(256) void attn_bf16s(
    const __nv_bfloat16* __restrict__ qkvh, const __nv_bfloat16* __restrict__ qkvl,
    const __nv_bfloat16* __restrict__ vth,  const __nv_bfloat16* __restrict__ vtl,
    float* __restrict__ ao)
{
    extern __shared__ __nv_bfloat16 sm[];
    const int tid = threadIdx.x;
    const int wid = tid >> 5, lane = tid & 31;
    const int gid = lane >> 2, tg = lane & 3;
    const int h = blockIdx.y, b = blockIdx.z;
    const int qrow = blockIdx.x * 128 + wid * 16;

    // ---- Q fragments (hi/lo) straight from gmem, kept in registers ----
    const __nv_bfloat16* Qph = qkvh + (size_t)(b*TT + qrow) * QKV_N + h*HD;
    const __nv_bfloat16* Qpl = qkvl + (size_t)(b*TT + qrow) * QKV_N + h*HD;
    uint32_t qh[4][4], ql[4][4];
#pragma unroll
    for (int kk = 0; kk < 4; kk++) {
        int kb = kk*16 + 2*tg;
        qh[kk][0] = *reinterpret_cast<const uint32_t*>(Qph + (size_t)gid*QKV_N + kb);
        qh[kk][1] = *reinterpret_cast<const uint32_t*>(Qph + (size_t)(gid+8)*QKV_N + kb);
        qh[kk][2] = *reinterpret_cast<const uint32_t*>(Qph + (size_t)gid*QKV_N + kb + 8);
        qh[kk][3] = *reinterpret_cast<const uint32_t*>(Qph + (size_t)(gid+8)*QKV_N + kb + 8);
        ql[kk][0] = *reinterpret_cast<const uint32_t*>(Qpl + (size_t)gid*QKV_N + kb);
        ql[kk][1] = *reinterpret_cast<const uint32_t*>(Qpl + (size_t)(gid+8)*QKV_N + kb);
        ql[kk][2] = *reinterpret_cast<const uint32_t*>(Qpl + (size_t)gid*QKV_N + kb + 8);
        ql[kk][3] = *reinterpret_cast<const uint32_t*>(Qpl + (size_t)(gid+8)*QKV_N + kb + 8);
    }

    float m0 = -1e30f, m1 = -1e30f, l0 = 0.f, l1 = 0.f;
    float o[8][4];
#pragma unroll
    for (int nt = 0; nt < 8; nt++)
#pragma unroll
        for (int i = 0; i < 4; i++) o[nt][i] = 0.f;

    const __nv_bfloat16* Kgh = qkvh + (size_t)(b*TT)*QKV_N + DM + h*HD;
    const __nv_bfloat16* Kgl = qkvl + (size_t)(b*TT)*QKV_N + DM + h*HD;
    const __nv_bfloat16* Vgh = vth + (size_t)(b*HH + h)*HD*TT;
    const __nv_bfloat16* Vgl = vtl + (size_t)(b*HH + h)*HD*TT;

    auto issue = [&](int kt, int buf) {
        __nv_bfloat16* s = sm + buf * ABUF;
#pragma unroll
        for (int t = 0; t < 2; t++) {
            int e = tid + t * 256;
            int r = e >> 3, c = (e & 7) * 8;
            cpasync16(s +             r*APAD + c, Kgh + (size_t)(kt*64 + r)*QKV_N + c);
            cpasync16(s + 64*APAD   + r*APAD + c, Kgl + (size_t)(kt*64 + r)*QKV_N + c);
            cpasync16(s + 2*64*APAD + r*APAD + c, Vgh + (size_t)r*TT + kt*64 + c);
            cpasync16(s + 3*64*APAD + r*APAD + c, Vgl + (size_t)r*TT + kt*64 + c);
        }
    };

    const int NKT = TT / 64;   // 32
    issue(0, 0); CP_COMMIT;

    const float sc = 1.0f / (float)HD;

    for (int kt = 0; kt < NKT; kt++) {
        int buf = kt & 1;
        if (kt + 1 < NKT) { issue(kt + 1, buf ^ 1); CP_COMMIT; CP_WAIT1; }
        else              { CP_WAIT0; }
        __syncthreads();

        const __nv_bfloat16* sKh = sm + buf * ABUF;
        const __nv_bfloat16* sKl = sKh + 64*APAD;
        const __nv_bfloat16* sVh = sKh + 2*64*APAD;
        const __nv_bfloat16* sVl = sKh + 3*64*APAD;

        // ---- S = Q K^T (split bf16) ----
        float s[8][4];
#pragma unroll
        for (int nt = 0; nt < 8; nt++)
#pragma unroll
            for (int i = 0; i < 4; i++) s[nt][i] = 0.f;

#pragma unroll
        for (int kk = 0; kk < 4; kk++) {
            int kb = kk*16 + 2*tg;
#pragma unroll
            for (int nt = 0; nt < 8; nt++) {
                int rn = nt*8 + gid;
                uint32_t bhf[2], blf[2];
                bhf[0] = lds32(sKh + rn*APAD + kb);
                bhf[1] = lds32(sKh + rn*APAD + kb + 8);
                blf[0] = lds32(sKl + rn*APAD + kb);
                blf[1] = lds32(sKl + rn*APAD + kb + 8);
                mma16816(s[nt], qh[kk], bhf);
                mma16816(s[nt], qh[kk], blf);
                mma16816(s[nt], ql[kk], bhf);
            }
        }

        // ---- online softmax (scale folded in) ----
        float rm0 = -1e30f, rm1 = -1e30f;
#pragma unroll
        for (int nt = 0; nt < 8; nt++) {
            rm0 = fmaxf(rm0, fmaxf(s[nt][0], s[nt][1]));
            rm1 = fmaxf(rm1, fmaxf(s[nt][2], s[nt][3]));
        }
        rm0 = fmaxf(rm0, __shfl_xor_sync(0xffffffffu, rm0, 1));
        rm0 = fmaxf(rm0, __shfl_xor_sync(0xffffffffu, rm0, 2));
        rm1 = fmaxf(rm1, __shfl_xor_sync(0xffffffffu, rm1, 1));
        rm1 = fmaxf(rm1, __shfl_xor_sync(0xffffffffu, rm1, 2));

        float m0n = fmaxf(m0, rm0 * sc);
        float m1n = fmaxf(m1, rm1 * sc);
        float c0 = __expf(m0 - m0n), c1 = __expf(m1 - m1n);
        float rs0 = 0.f, rs1 = 0.f;
#pragma unroll
        for (int nt = 0; nt < 8; nt++) {
            s[nt][0] = __expf(fmaf(s[nt][0], sc, -m0n)); rs0 += s[nt][0];
            s[nt][1] = __expf(fmaf(s[nt][1], sc, -m0n)); rs0 += s[nt][1];
            s[nt][2] = __expf(fmaf(s[nt][2], sc, -m1n)); rs1 += s[nt][2];
            s[nt][3] = __expf(fmaf(s[nt][3], sc, -m1n)); rs1 += s[nt][3];
        }
        rs0 += __shfl_xor_sync(0xffffffffu, rs0, 1);
        rs0 += __shfl_xor_sync(0xffffffffu, rs0, 2);
        rs1 += __shfl_xor_sync(0xffffffffu, rs1, 1);
        rs1 += __shfl_xor_sync(0xffffffffu, rs1, 2);
        l0 = l0 * c0 + rs0; m0 = m0n;
        l1 = l1 * c1 + rs1; m1 = m1n;
#pragma unroll
        for (int nt = 0; nt < 8; nt++) {
            o[nt][0] *= c0; o[nt][1] *= c0;
            o[nt][2] *= c1; o[nt][3] *= c1;
        }

        // ---- P fragments (register->register, split) ----
        uint32_t ph[4][4], pl[4][4];
#pragma unroll
        for (int kk = 0; kk < 4; kk++) {
            int j0 = 2*kk, j1 = 2*kk + 1;
            split2(s[j0][0], s[j0][1], ph[kk][0], pl[kk][0]);
            split2(s[j0][2], s[j0][3], ph[kk][1], pl[kk][1]);
            split2(s[j1][0], s[j1][1], ph[kk][2], pl[kk][2]);
            split2(s[j1][2], s[j1][3], ph[kk][3], pl[kk][3]);
        }

        // ---- O += P V ----
#pragma unroll
        for (int kk = 0; kk < 4; kk++) {
            int kb = kk*16 + 2*tg;
#pragma unroll
            for (int nt = 0; nt < 8; nt++) {
                int rn = nt*8 + gid;
                uint32_t bhf[2], blf[2];
                bhf[0] = lds32(sVh + rn*APAD + kb);
                bhf[1] = lds32(sVh + rn*APAD + kb + 8);
                blf[0] = lds32(sVl + rn*APAD + kb);
                blf[1] = lds32(sVl + rn*APAD + kb + 8);
                mma16816(o[nt], ph[kk], bhf);
                mma16816(o[nt], ph[kk], blf);
                mma16816(o[nt], pl[kk], bhf);
            }
        }
        __syncthreads();
    }

    // ---- epilogue ----
    float inv0 = 1.0f / l0, inv1 = 1.0f / l1;
    float* aop = ao + (size_t)(b*TT + qrow + gid) * DM + h*HD;
#pragma unroll
    for (int nt = 0; nt < 8; nt++) {
        int c = nt*8 + 2*tg;
        float2 v0 = make_float2(o[nt][0]*inv0, o[nt][1]*inv0);
        float2 v1 = make_float2(o[nt][2]*inv1, o[nt][3]*inv1);
        *reinterpret_cast<float2*>(aop + c)          = v0;
        *reinterpret_cast<float2*>(aop + 8*DM + c)   = v1;
    }
}

// ---------------------------------------------------------------------------
// Launch
// ---------------------------------------------------------------------------
extern "C" void kernel_launch(void* const* d_in, const int* in_sizes, int n_in,
                              void* d_out, int out_size)
{
    const float* x     = (const float*)d_in[0];
    const float* wqkv  = (const float*)d_in[1];
    const float* wproj = (const float*)d_in[2];
    float* out = (float*)d_out;

    float *qkv, *ao;
    __nv_bfloat16 *xh, *xl, *wqh, *wql, *wph, *wpl, *kh, *kl, *vth, *vtl, *aoh, *aol;
    cudaGetSymbolAddress((void**)&qkv, g_qkv);
    cudaGetSymbolAddress((void**)&ao,  g_ao);
    cudaGetSymbolAddress((void**)&xh,  g_xh);   cudaGetSymbolAddress((void**)&xl,  g_xl);
    cudaGetSymbolAddress((void**)&wqh, g_wqkvh); cudaGetSymbolAddress((void**)&wql, g_wqkvl);
    cudaGetSymbolAddress((void**)&wph, g_wprojh); cudaGetSymbolAddress((void**)&wpl, g_wprojl);
    cudaGetSymbolAddress((void**)&kh,  g_qkvh); cudaGetSymbolAddress((void**)&kl,  g_qkvl);
    cudaGetSymbolAddress((void**)&vth, g_vth);  cudaGetSymbolAddress((void**)&vtl, g_vtl);
    cudaGetSymbolAddress((void**)&aoh, g_aoh);  cudaGetSymbolAddress((void**)&aol, g_aol);

    static bool attr_set = false;
    if (!attr_set) {
        cudaFuncSetAttribute(gemm_bf16s, cudaFuncAttributeMaxDynamicSharedMemorySize, 2*GBUF*2);
        cudaFuncSetAttribute(attn_bf16s, cudaFuncAttributeMaxDynamicSharedMemorySize, 2*ABUF*2);
        attr_set = true;
    }

    // 1) split x
    cvt_split<<<(MROWS*DM/4 + 255)/256, 256>>>((const float4*)x,
        (__nv_bfloat162*)xh, (__nv_bfloat162*)xl, MROWS*DM/4);
    // 2) split + transpose weights
    cvt_wT<<<dim3(QKV_N/32, DM/32), dim3(32,8)>>>(wqkv, wqh, wql, DM, QKV_N);
    cvt_wT<<<dim3(DM/32, DM/32),   dim3(32,8)>>>(wproj, wph, wpl, DM, DM);
    // 3) QKV GEMM
    gemm_bf16s<<<dim3(QKV_N/128, MROWS/128), 256, 2*GBUF*2>>>(
        xh, xl, wqh, wql, qkv, MROWS, QKV_N, DM);
    // 4) split qkv + build V^T
    cvt_split<<<(MROWS*QKV_N/4 + 255)/256, 256>>>((const float4*)qkv,
        (__nv_bfloat162*)kh, (__nv_bfloat162*)kl, MROWS*QKV_N/4);
    cvt_vT<<<dim3(TT/32, HD/32, BB*HH), dim3(32,8)>>>(qkv, vth, vtl);
    // 5) attention
    attn_bf16s<<<dim3(TT/128, HH, BB), 256, 2*ABUF*2>>>(kh, kl, vth, vtl, ao);
    // 6) split ao + projection
    cvt_split<<<(MROWS*DM/4 + 255)/256, 256>>>((const float4*)ao,
        (__nv_bfloat162*)aoh, (__nv_bfloat162*)aol, MROWS*DM/4);
    gemm_bf16s<<<dim3(DM/128, MROWS/128), 256, 2*GBUF*2>>>(
        aoh, aol, wph, wpl, out, MROWS, DM, DM);
}

// round 7
// speedup vs baseline: 5.5278x; 1.0399x over previous
#include <cuda_runtime.h>
#include <cuda_bf16.h>
#include <cstdint>

// Problem constants
#define BB 2
#define TT 2048
#define DM 1024
#define HH 16
#define HD 64
#define MROWS (BB*TT)          // 4096
#define QKV_N (3*DM)           // 3072

// ---------------------------------------------------------------------------
// Device scratch
// ---------------------------------------------------------------------------
__device__ __nv_bfloat16 g_xh[(size_t)MROWS * DM],  g_xl[(size_t)MROWS * DM];
__device__ __nv_bfloat16 g_wqkvh[(size_t)QKV_N * DM], g_wqkvl[(size_t)QKV_N * DM];   // [N][K]
__device__ __nv_bfloat16 g_wprojh[(size_t)DM * DM],  g_wprojl[(size_t)DM * DM];      // [N][K]
__device__ __nv_bfloat16 g_qkvh[(size_t)MROWS * QKV_N], g_qkvl[(size_t)MROWS * QKV_N];
__device__ __nv_bfloat16 g_vth[(size_t)BB*HH*HD*TT], g_vtl[(size_t)BB*HH*HD*TT];     // [b,h,d,t]
__device__ __nv_bfloat16 g_aoh[(size_t)MROWS * DM], g_aol[(size_t)MROWS * DM];

// ---------------------------------------------------------------------------
// Helpers
// ---------------------------------------------------------------------------
__device__ __forceinline__ uint32_t lds32(const __nv_bfloat16* p) {
    return *reinterpret_cast<const uint32_t*>(p);
}
__device__ __forceinline__ void cpasync16g(void* smem_ptr, const void* gptr) {
    uint32_t s = (uint32_t)__cvta_generic_to_shared(smem_ptr);
    asm volatile("cp.async.cg.shared.global [%0], [%1], 16;\n" :: "r"(s), "l"(gptr));
}
#define CP_COMMIT asm volatile("cp.async.commit_group;\n")
#define CP_WAIT1  asm volatile("cp.async.wait_group 1;\n")
#define CP_WAIT0  asm volatile("cp.async.wait_group 0;\n")

__device__ __forceinline__ void mma16816(float* d, const uint32_t* a, const uint32_t* b) {
    asm volatile(
        "mma.sync.aligned.m16n8k16.row.col.f32.bf16.bf16.f32 "
        "{%0,%1,%2,%3}, {%4,%5,%6,%7}, {%8,%9}, {%0,%1,%2,%3};\n"
        : "+f"(d[0]), "+f"(d[1]), "+f"(d[2]), "+f"(d[3])
        : "r"(a[0]), "r"(a[1]), "r"(a[2]), "r"(a[3]), "r"(b[0]), "r"(b[1]));
}

__device__ __forceinline__ void split2(float x, float y, uint32_t& h, uint32_t& l) {
    __nv_bfloat162 hv, lv;
    hv.x = __float2bfloat16_rn(x);
    hv.y = __float2bfloat16_rn(y);
    lv.x = __float2bfloat16_rn(x - __bfloat162float(hv.x));
    lv.y = __float2bfloat16_rn(y - __bfloat162float(hv.y));
    h = reinterpret_cast<uint32_t&>(hv);
    l = reinterpret_cast<uint32_t&>(lv);
}

// ---------------------------------------------------------------------------
// Split-bf16 HMMA GEMM: C[M,N] = A@B; A hi/lo [M,K], B hi/lo [N,K] k-major.
// 128x128 CTA tile, 128 threads = 4 warps (2x2), warp tile 64x64.
// k-step 32, cp.async double buffer. SPLIT: write hi/lo bf16, else fp32.
// ---------------------------------------------------------------------------
#define GPAD 40
#define GMAT (128*GPAD)         // elems per matrix tile (padded)
#define GSTAGE (4*GMAT)         // Ah|Al|Bh|Bl
#define GEMM_DSM (2*GSTAGE*2)   // bytes (2 stages)

template<bool SPLIT>
__global__ __launch_bounds__(128, 2) void hgemm(
    const __nv_bfloat16* __restrict__ Ah, const __nv_bfloat16* __restrict__ Al,
    const __nv_bfloat16* __restrict__ Bh, const __nv_bfloat16* __restrict__ Bl,
    float* __restrict__ Cf,
    __nv_bfloat16* __restrict__ Ch, __nv_bfloat16* __restrict__ Cl,
    int M, int N, int K)
{
    extern __shared__ __nv_bfloat16 sm[];
    const int tid  = threadIdx.x;
    const int wid  = tid >> 5, lane = tid & 31;
    const int gid  = lane >> 2, tg = lane & 3;
    const int wm   = wid & 1,  wn  = wid >> 1;
    const int m0   = blockIdx.y * 128, n0 = blockIdx.x * 128;
    const int NS   = K >> 5;

    float acc[4][8][4];
#pragma unroll
    for (int mt = 0; mt < 4; mt++)
#pragma unroll
        for (int nt = 0; nt < 8; nt++)
#pragma unroll
            for (int i = 0; i < 4; i++) acc[mt][nt][i] = 0.f;

    auto issue = [&](int ks, int buf) {
        __nv_bfloat16* s = sm + buf * GSTAGE;
        const int k0 = ks * 32;
        const __nv_bfloat16* srcs[4] = {
            Ah + (size_t)m0 * K + k0, Al + (size_t)m0 * K + k0,
            Bh + (size_t)n0 * K + k0, Bl + (size_t)n0 * K + k0 };
#pragma unroll
        for (int mat = 0; mat < 4; mat++) {
            const __nv_bfloat16* base = srcs[mat];
            __nv_bfloat16* smat = s + mat * GMAT;
#pragma unroll
            for (int j = 0; j < 4; j++) {
                int e = tid + j * 128;          // 0..511
                int r = e >> 2;                 // 0..127
                int c = (e & 3) * 8;            // 0,8,16,24
                cpasync16g(smat + r*GPAD + c, base + (size_t)r * K + c);
            }
        }
    };

    issue(0, 0); CP_COMMIT;

    for (int ks = 0; ks < NS; ks++) {
        int buf = ks & 1;
        if (ks + 1 < NS) { issue(ks + 1, buf ^ 1); CP_COMMIT; CP_WAIT1; }
        else             { CP_WAIT0; }
        __syncthreads();

        const __nv_bfloat16* sAh = sm + buf * GSTAGE;
        const __nv_bfloat16* sAl = sAh + GMAT;
        const __nv_bfloat16* sBh = sAh + 2*GMAT;
        const __nv_bfloat16* sBl = sAh + 3*GMAT;

#pragma unroll
        for (int kt = 0; kt < 2; kt++) {
            int kb = kt * 16 + 2 * tg;
            uint32_t ah[4][4], al[4][4];
#pragma unroll
            for (int mt = 0; mt < 4; mt++) {
                int r = wm*64 + mt*16 + gid;
                ah[mt][0] = lds32(sAh + r*GPAD + kb);
                ah[mt][1] = lds32(sAh + (r+8)*GPAD + kb);
                ah[mt][2] = lds32(sAh + r*GPAD + kb + 8);
                ah[mt][3] = lds32(sAh + (r+8)*GPAD + kb + 8);
                al[mt][0] = lds32(sAl + r*GPAD + kb);
                al[mt][1] = lds32(sAl + (r+8)*GPAD + kb);
                al[mt][2] = lds32(sAl + r*GPAD + kb + 8);
                al[mt][3] = lds32(sAl + (r+8)*GPAD + kb + 8);
            }
            uint32_t bh[8][2], bl[8][2];
#pragma unroll
            for (int nt = 0; nt < 8; nt++) {
                int rn = wn*64 + nt*8 + gid;
                bh[nt][0] = lds32(sBh + rn*GPAD + kb);
                bh[nt][1] = lds32(sBh + rn*GPAD + kb + 8);
                bl[nt][0] = lds32(sBl + rn*GPAD + kb);
                bl[nt][1] = lds32(sBl + rn*GPAD + kb + 8);
            }
            // three split products, long reuse distance per accumulator
#pragma unroll
            for (int mt = 0; mt < 4; mt++)
#pragma unroll
                for (int nt = 0; nt < 8; nt++)
                    mma16816(acc[mt][nt], ah[mt], bh[nt]);
#pragma unroll
            for (int mt = 0; mt < 4; mt++)
#pragma unroll
                for (int nt = 0; nt < 8; nt++)
                    mma16816(acc[mt][nt], ah[mt], bl[nt]);
#pragma unroll
            for (int mt = 0; mt < 4; mt++)
#pragma unroll
                for (int nt = 0; nt < 8; nt++)
                    mma16816(acc[mt][nt], al[mt], bh[nt]);
        }
        __syncthreads();
    }

    // epilogue
#pragma unroll
    for (int mt = 0; mt < 4; mt++)
#pragma unroll
        for (int nt = 0; nt < 8; nt++) {
            int r = m0 + wm*64 + mt*16 + gid;
            int c = n0 + wn*64 + nt*8 + 2*tg;
            if (SPLIT) {
                uint32_t hh, ll;
                split2(acc[mt][nt][0], acc[mt][nt][1], hh, ll);
                *reinterpret_cast<uint32_t*>(Ch + (size_t)r*N + c) = hh;
                *reinterpret_cast<uint32_t*>(Cl + (size_t)r*N + c) = ll;
                split2(acc[mt][nt][2], acc[mt][nt][3], hh, ll);
                *reinterpret_cast<uint32_t*>(Ch + (size_t)(r+8)*N + c) = hh;
                *reinterpret_cast<uint32_t*>(Cl + (size_t)(r+8)*N + c) = ll;
            } else {
                *reinterpret_cast<float2*>(Cf + (size_t)r*N + c) =
                    make_float2(acc[mt][nt][0], acc[mt][nt][1]);
                *reinterpret_cast<float2*>(Cf + (size_t)(r+8)*N + c) =
                    make_float2(acc[mt][nt][2], acc[mt][nt][3]);
            }
        }
}

// ---------------------------------------------------------------------------
// Conversions
// ---------------------------------------------------------------------------
__global__ void cvt_split(const float4* __restrict__ in,
                          __nv_bfloat162* __restrict__ hi,
                          __nv_bfloat162* __restrict__ lo, int n4)
{
    int i = blockIdx.x * blockDim.x + threadIdx.x;
    if (i >= n4) return;
    float4 v = in[i];
    __nv_bfloat162 h0, h1, l0, l1;
    h0.x = __float2bfloat16_rn(v.x); h0.y = __float2bfloat16_rn(v.y);
    h1.x = __float2bfloat16_rn(v.z); h1.y = __float2bfloat16_rn(v.w);
    l0.x = __float2bfloat16_rn(v.x - __bfloat162float(h0.x));
    l0.y = __float2bfloat16_rn(v.y - __bfloat162float(h0.y));
    l1.x = __float2bfloat16_rn(v.z - __bfloat162float(h1.x));
    l1.y = __float2bfloat16_rn(v.w - __bfloat162float(h1.y));
    hi[2*i] = h0; hi[2*i+1] = h1;
    lo[2*i] = l0; lo[2*i+1] = l1;
}

// W [K,N] fp32 -> Wt hi/lo [N,K] bf16
__global__ void cvt_wT(const float* __restrict__ w,
                       __nv_bfloat16* __restrict__ th,
                       __nv_bfloat16* __restrict__ tl, int K, int N)
{
    __shared__ float t[32][33];
    int bx = blockIdx.x, by = blockIdx.y;
    int tx = threadIdx.x, ty = threadIdx.y;
#pragma unroll
    for (int j = 0; j < 32; j += 8)
        t[ty + j][tx] = w[(size_t)(by*32 + ty + j) * N + bx*32 + tx];
    __syncthreads();
#pragma unroll
    for (int j = 0; j < 32; j += 8) {
        float v = t[tx][ty + j];
        size_t o = (size_t)(bx*32 + ty + j) * K + by*32 + tx;
        __nv_bfloat16 h = __float2bfloat16_rn(v);
        th[o] = h;
        tl[o] = __float2bfloat16_rn(v - __bfloat162float(h));
    }
}

// V hi/lo transpose: g_qkvh/l [t, 2048 + h*64 + d] -> g_vth/l [(b,h,d), t]
__global__ void cvt_vT2(const __nv_bfloat16* __restrict__ qh,
                        const __nv_bfloat16* __restrict__ ql,
                        __nv_bfloat16* __restrict__ th,
                        __nv_bfloat16* __restrict__ tl)
{
    __shared__ __nv_bfloat16 t1[32][33], t2[32][33];
    int bh = blockIdx.z;
    int b = bh >> 4, h = bh & 15;
    int t0 = blockIdx.x * 32, d0 = blockIdx.y * 32;
    int tx = threadIdx.x, ty = threadIdx.y;
#pragma unroll
    for (int j = 0; j < 32; j += 8) {
        size_t src = (size_t)(b*TT + t0 + ty + j) * QKV_N + 2*DM + h*HD + d0 + tx;
        t1[ty + j][tx] = qh[src];
        t2[ty + j][tx] = ql[src];
    }
    __syncthreads();
#pragma unroll
    for (int j = 0; j < 32; j += 8) {
        size_t o = (size_t)(bh*HD + d0 + ty + j) * TT + t0 + tx;
        th[o] = t1[tx][ty + j];
        tl[o] = t2[tx][ty + j];
    }
}

// ---------------------------------------------------------------------------
// Flash attention, split-bf16 HMMA. 256 threads, 8 warps x 16 q-rows.
// Epilogue writes split hi/lo bf16 directly.
// ---------------------------------------------------------------------------
#define APAD 72
#define ABUF (4*64*APAD)

__global__ __launch_bounds__(256, 2) void attn_bf16s(
    const __nv_bfloat16* __restrict__ qkvh, const __nv_bfloat16* __restrict__ qkvl,
    const __nv_bfloat16* __restrict__ vth,  const __nv_bfloat16* __restrict__ vtl,
    __nv_bfloat16* __restrict__ aoh, __nv_bfloat16* __restrict__ aol)
{
    extern __shared__ __nv_bfloat16 smA[];
    const int tid = threadIdx.x;
    const int wid = tid >> 5, lane = tid & 31;
    const int gid = lane >> 2, tg = lane & 3;
    const int h = blockIdx.y, b = blockIdx.z;
    const int qrow = blockIdx.x * 128 + wid * 16;

    const __nv_bfloat16* Qph = qkvh + (size_t)(b*TT + qrow) * QKV_N + h*HD;
    const __nv_bfloat16* Qpl = qkvl + (size_t)(b*TT + qrow) * QKV_N + h*HD;
    uint32_t qh[4][4], ql[4][4];
#pragma unroll
    for (int kk = 0; kk < 4; kk++) {
        int kb = kk*16 + 2*tg;
        qh[kk][0] = *reinterpret_cast<const uint32_t*>(Qph + (size_t)gid*QKV_N + kb);
        qh[kk][1] = *reinterpret_cast<const uint32_t*>(Qph + (size_t)(gid+8)*QKV_N + kb);
        qh[kk][2] = *reinterpret_cast<const uint32_t*>(Qph + (size_t)gid*QKV_N + kb + 8);
        qh[kk][3] = *reinterpret_cast<const uint32_t*>(Qph + (size_t)(gid+8)*QKV_N + kb + 8);
        ql[kk][0] = *reinterpret_cast<const uint32_t*>(Qpl + (size_t)gid*QKV_N + kb);
        ql[kk][1] = *reinterpret_cast<const uint32_t*>(Qpl + (size_t)(gid+8)*QKV_N + kb);
        ql[kk][2] = *reinterpret_cast<const uint32_t*>(Qpl + (size_t)gid*QKV_N + kb + 8);
        ql[kk][3] = *reinterpret_cast<const uint32_t*>(Qpl + (size_t)(gid+8)*QKV_N + kb + 8);
    }

    float m0 = -1e30f, m1 = -1e30f, l0 = 0.f, l1 = 0.f;
    float o[8][4];
#pragma unroll
    for (int nt = 0; nt < 8; nt++)
#pragma unroll
        for (int i = 0; i < 4; i++) o[nt][i] = 0.f;

    const __nv_bfloat16* Kgh = qkvh + (size_t)(b*TT)*QKV_N + DM + h*HD;
    const __nv_bfloat16* Kgl = qkvl + (size_t)(b*TT)*QKV_N + DM + h*HD;
    const __nv_bfloat16* Vgh = vth + (size_t)(b*HH + h)*HD*TT;
    const __nv_bfloat16* Vgl = vtl + (size_t)(b*HH + h)*HD*TT;

    auto issue = [&](int kt, int buf) {
        __nv_bfloat16* s = smA + buf * ABUF;
#pragma unroll
        for (int t = 0; t < 2; t++) {
            int e = tid + t * 256;
            int r = e >> 3, c = (e & 7) * 8;
            cpasync16g(s +             r*APAD + c, Kgh + (size_t)(kt*64 + r)*QKV_N + c);
            cpasync16g(s + 64*APAD   + r*APAD + c, Kgl + (size_t)(kt*64 + r)*QKV_N + c);
            cpasync16g(s + 2*64*APAD + r*APAD + c, Vgh + (size_t)r*TT + kt*64 + c);
            cpasync16g(s + 3*64*APAD + r*APAD + c, Vgl + (size_t)r*TT + kt*64 + c);
        }
    };

    const int NKT = TT / 64;
    issue(0, 0); CP_COMMIT;

    const float sc = 1.0f / (float)HD;

    for (int kt = 0; kt < NKT; kt++) {
        int buf = kt & 1;
        if (kt + 1 < NKT) { issue(kt + 1, buf ^ 1); CP_COMMIT; CP_WAIT1; }
        else              { CP_WAIT0; }
        __syncthreads();

        const __nv_bfloat16* sKh = smA + buf * ABUF;
        const __nv_bfloat16* sKl = sKh + 64*APAD;
        const __nv_bfloat16* sVh = sKh + 2*64*APAD;
        const __nv_bfloat16* sVl = sKh + 3*64*APAD;

        float s[8][4];
#pragma unroll
        for (int nt = 0; nt < 8; nt++)
#pragma unroll
            for (int i = 0; i < 4; i++) s[nt][i] = 0.f;

#pragma unroll
        for (int kk = 0; kk < 4; kk++) {
            int kb = kk*16 + 2*tg;
#pragma unroll
            for (int nt = 0; nt < 8; nt++) {
                int rn = nt*8 + gid;
                uint32_t bhf[2], blf[2];
                bhf[0] = lds32(sKh + rn*APAD + kb);
                bhf[1] = lds32(sKh + rn*APAD + kb + 8);
                blf[0] = lds32(sKl + rn*APAD + kb);
                blf[1] = lds32(sKl + rn*APAD + kb + 8);
                mma16816(s[nt], qh[kk], bhf);
                mma16816(s[nt], qh[kk], blf);
                mma16816(s[nt], ql[kk], bhf);
            }
        }

        float rm0 = -1e30f, rm1 = -1e30f;
#pragma unroll
        for (int nt = 0; nt < 8; nt++) {
            rm0 = fmaxf(rm0, fmaxf(s[nt][0], s[nt][1]));
            rm1 = fmaxf(rm1, fmaxf(s[nt][2], s[nt][3]));
        }
        rm0 = fmaxf(rm0, __shfl_xor_sync(0xffffffffu, rm0, 1));
        rm0 = fmaxf(rm0, __shfl_xor_sync(0xffffffffu, rm0, 2));
        rm1 = fmaxf(rm1, __shfl_xor_sync(0xffffffffu, rm1, 1));
        rm1 = fmaxf(rm1, __shfl_xor_sync(0xffffffffu, rm1, 2));

        float m0n = fmaxf(m0, rm0 * sc);
        float m1n = fmaxf(m1, rm1 * sc);
        float c0 = __expf(m0 - m0n), c1 = __expf(m1 - m1n);
        float rs0 = 0.f, rs1 = 0.f;
#pragma unroll
        for (int nt = 0; nt < 8; nt++) {
            s[nt][0] = __expf(fmaf(s[nt][0], sc, -m0n)); rs0 += s[nt][0];
            s[nt][1] = __expf(fmaf(s[nt][1], sc, -m0n)); rs0 += s[nt][1];
            s[nt][2] = __expf(fmaf(s[nt][2], sc, -m1n)); rs1 += s[nt][2];
            s[nt][3] = __expf(fmaf(s[nt][3], sc, -m1n)); rs1 += s[nt][3];
        }
        rs0 += __shfl_xor_sync(0xffffffffu, rs0, 1);
        rs0 += __shfl_xor_sync(0xffffffffu, rs0, 2);
        rs1 += __shfl_xor_sync(0xffffffffu, rs1, 1);
        rs1 += __shfl_xor_sync(0xffffffffu, rs1, 2);
        l0 = l0 * c0 + rs0; m0 = m0n;
        l1 = l1 * c1 + rs1; m1 = m1n;
#pragma unroll
        for (int nt = 0; nt < 8; nt++) {
            o[nt][0] *= c0; o[nt][1] *= c0;
            o[nt][2] *= c1; o[nt][3] *= c1;
        }

        uint32_t ph[4][4], pl[4][4];
#pragma unroll
        for (int kk = 0; kk < 4; kk++) {
            int j0 = 2*kk, j1 = 2*kk + 1;
            split2(s[j0][0], s[j0][1], ph[kk][0], pl[kk][0]);
            split2(s[j0][2], s[j0][3], ph[kk][1], pl[kk][1]);
            split2(s[j1][0], s[j1][1], ph[kk][2], pl[kk][2]);
            split2(s[j1][2], s[j1][3], ph[kk][3], pl[kk][3]);
        }

#pragma unroll
        for (int kk = 0; kk < 4; kk++) {
            int kb = kk*16 + 2*tg;
#pragma unroll
            for (int nt = 0; nt < 8; nt++) {
                int rn = nt*8 + gid;
                uint32_t bhf[2], blf[2];
                bhf[0] = lds32(sVh + rn*APAD + kb);
                bhf[1] = lds32(sVh + rn*APAD + kb + 8);
                blf[0] = lds32(sVl + rn*APAD + kb);
                blf[1] = lds32(sVl + rn*APAD + kb + 8);
                mma16816(o[nt], ph[kk], bhf);
                mma16816(o[nt], ph[kk], blf);
                mma16816(o[nt], pl[kk], bhf);
            }
        }
        __syncthreads();
    }

    // epilogue: split ao directly to hi/lo bf16
    float inv0 = 1.0f / l0, inv1 = 1.0f / l1;
    __nv_bfloat16* oph = aoh + (size_t)(b*TT + qrow + gid) * DM + h*HD;
    __nv_bfloat16* opl = aol + (size_t)(b*TT + qrow + gid) * DM + h*HD;
#pragma unroll
    for (int nt = 0; nt < 8; nt++) {
        int c = nt*8 + 2*tg;
        uint32_t hh, ll;
        split2(o[nt][0]*inv0, o[nt][1]*inv0, hh, ll);
        *reinterpret_cast<uint32_t*>(oph + c) = hh;
        *reinterpret_cast<uint32_t*>(opl + c) = ll;
        split2(o[nt][2]*inv1, o[nt][3]*inv1, hh, ll);
        *reinterpret_cast<uint32_t*>(oph + (size_t)8*DM + c) = hh;
        *reinterpret_cast<uint32_t*>(opl + (size_t)8*DM + c) = ll;
    }
}

// ---------------------------------------------------------------------------
// Launch
// ---------------------------------------------------------------------------
extern "C" void kernel_launch(void* const* d_in, const int* in_sizes, int n_in,
                              void* d_out, int out_size)
{
    const float* x     = (const float*)d_in[0];
    const float* wqkv  = (const float*)d_in[1];
    const float* wproj = (const float*)d_in[2];
    float* out = (float*)d_out;

    __nv_bfloat16 *xh, *xl, *wqh, *wql, *wph, *wpl, *kh, *kl, *vth, *vtl, *aoh, *aol;
    cudaGetSymbolAddress((void**)&xh,  g_xh);    cudaGetSymbolAddress((void**)&xl,  g_xl);
    cudaGetSymbolAddress((void**)&wqh, g_wqkvh); cudaGetSymbolAddress((void**)&wql, g_wqkvl);
    cudaGetSymbolAddress((void**)&wph, g_wprojh);cudaGetSymbolAddress((void**)&wpl, g_wprojl);
    cudaGetSymbolAddress((void**)&kh,  g_qkvh);  cudaGetSymbolAddress((void**)&kl,  g_qkvl);
    cudaGetSymbolAddress((void**)&vth, g_vth);   cudaGetSymbolAddress((void**)&vtl, g_vtl);
    cudaGetSymbolAddress((void**)&aoh, g_aoh);   cudaGetSymbolAddress((void**)&aol, g_aol);

    static bool attr_set = false;
    if (!attr_set) {
        cudaFuncSetAttribute(hgemm<true>,  cudaFuncAttributeMaxDynamicSharedMemorySize, GEMM_DSM);
        cudaFuncSetAttribute(hgemm<false>, cudaFuncAttributeMaxDynamicSharedMemorySize, GEMM_DSM);
        cudaFuncSetAttribute(attn_bf16s, cudaFuncAttributeMaxDynamicSharedMemorySize, 2*ABUF*2);
        attr_set = true;
    }

    // 1) split x
    cvt_split<<<(MROWS*DM/4 + 255)/256, 256>>>((const float4*)x,
        (__nv_bfloat162*)xh, (__nv_bfloat162*)xl, MROWS*DM/4);
    // 2) split + transpose weights
    cvt_wT<<<dim3(QKV_N/32, DM/32), dim3(32,8)>>>(wqkv, wqh, wql, DM, QKV_N);
    cvt_wT<<<dim3(DM/32, DM/32),   dim3(32,8)>>>(wproj, wph, wpl, DM, DM);
    // 3) QKV GEMM, writes split hi/lo bf16 directly
    hgemm<true><<<dim3(QKV_N/128, MROWS/128), 128, GEMM_DSM>>>(
        xh, xl, wqh, wql, nullptr, kh, kl, MROWS, QKV_N, DM);
    // 4) transpose V hi/lo
    cvt_vT2<<<dim3(TT/32, HD/32, BB*HH), dim3(32,8)>>>(kh, kl, vth, vtl);
    // 5) attention (writes split bf16 ao)
    attn_bf16s<<<dim3(TT/128, HH, BB), 256, 2*ABUF*2>>>(kh, kl, vth, vtl, aoh, aol);
    // 6) projection, fp32 out
    hgemm<false><<<dim3(DM/128, MROWS/128), 128, GEMM_DSM>>>(
        aoh, aol, wph, wpl, out, nullptr, nullptr, MROWS, DM, DM);
}